// round 4
// baseline (speedup 1.0000x reference)
#include <cuda_runtime.h>
#include <cstdint>

// ============================================================================
// EdgeMLP: concat -> GEMM1(tf32 mma.sync) -> LayerNorm -> SiLU ->
//          GEMM2(tf32 mma.sync) -> SiLU -> out
// Baseline-PTX only (no sm_103a features; toolchain emits .target sm_103).
// 1 CTA = 128 rows. 256 threads = 8 warps in 4(M) x 2(N) layout.
// All operands staged in SMEM in mma-fragment layout with bank-rotation skew.
// ============================================================================

#define TILE_M 128
#define KD1    192
#define ND     128
#define NKS1   24     // 192/8 k-steps for GEMM1
#define NKS2   16     // 128/8 k-steps for GEMM2

// dynamic SMEM layout (float offsets)
#define R0_OFF   0        // 24576 floats: A1 frags -> reused as A2 frags (16384)
#define R1_OFF   24576    // 24576 floats: B1 frags -> reused as W2 frags (16384)
#define MISC_OFF 49152    // b1,g,be,b2 (4*128) + red (512)
#define SMEM_FLOATS (49152 + 512 + 512)
#define SMEM_BYTES  (SMEM_FLOATS * 4)

static __device__ __forceinline__ uint32_t f2tf32(float f) {
    uint32_t r;
    asm("cvt.rna.tf32.f32 %0, %1;" : "=r"(r) : "f"(f));
    return r;
}
static __device__ __forceinline__ float silu_f(float x) {
    return x / (1.f + __expf(-x));
}
static __device__ __forceinline__ void mma8(float* c, const uint32_t* a,
                                            uint32_t b0, uint32_t b1) {
    asm volatile(
        "mma.sync.aligned.m16n8k8.row.col.f32.tf32.tf32.f32 "
        "{%0,%1,%2,%3},{%4,%5,%6,%7},{%8,%9},{%0,%1,%2,%3};\n"
        : "+f"(c[0]), "+f"(c[1]), "+f"(c[2]), "+f"(c[3])
        : "r"(a[0]), "r"(a[1]), "r"(a[2]), "r"(a[3]), "r"(b0), "r"(b1));
}

// Fragment-layout addressing.
// A-side region: idx = ((mt*NKS + ks)*4 + reg)*32 + posA
//   posA = (lane_frag + 4*(ks&7) + 16*(reg>>1)) & 31   (bank-rotation skew)
//   lane_frag = (row&7)*4 + (col&3); reg = (row>>3)&1 | ((col>>2)&1)<<1
// B-side region: idx = ((nb*NKS + ks)*2 + reg)*32 + posB
//   posB = (lane_frag + 4*(nb&7) + 16*((nb>>3)&1)) & 31
//   lane_frag = (n&7)*4 + (k&3); reg = (k>>2)&1

__global__ void __launch_bounds__(256, 1)
edge_mlp_kernel(const float* __restrict__ src, const float* __restrict__ edge,
                const float* __restrict__ W1, const float* __restrict__ b1,
                const float* __restrict__ gamma, const float* __restrict__ beta,
                const float* __restrict__ W2, const float* __restrict__ b2,
                float* __restrict__ out, int E) {
    extern __shared__ float sm[];
    float* s_b1 = sm + MISC_OFF;
    float* s_g  = s_b1 + 128;
    float* s_be = s_g + 128;
    float* s_b2 = s_be + 128;
    float* red  = s_b2 + 128;     // [stat(2)][nw(2)][row(128)]

    uint32_t* RAu = (uint32_t*)(sm + R0_OFF);
    uint32_t* RBu = (uint32_t*)(sm + R1_OFF);

    const int tid  = threadIdx.x;
    const int lane = tid & 31;
    const int wid  = tid >> 5;
    const int mw   = wid >> 1;    // 0..3 : rows 32*mw .. 32*mw+31
    const int nw   = wid & 1;     // 0..1 : cols 64*nw .. 64*nw+63
    const int g    = lane >> 2;
    const int tig  = lane & 3;
    const int mt0  = mw * 2;
    const int nb0  = nw * 8;

    const long long r0 = (long long)blockIdx.x * TILE_M;

    // ---------------- stage A1 (concat src|edge) as tf32 fragments ----------
    for (int i = tid; i < TILE_M * 32; i += 256) {
        int row = i >> 5;
        int c4  = (i & 31) << 2;
        long long gr = r0 + row;
        float4 v = (gr < E) ? __ldg((const float4*)(src + gr * 128 + c4))
                            : make_float4(0.f, 0.f, 0.f, 0.f);
        int ks = c4 >> 3;
        int rg = ((row >> 3) & 1) | (((c4 >> 2) & 1) << 1);
        int p  = (((row & 7) << 2) + 4 * (ks & 7) + ((rg & 2) << 3)) & 31;
        uint4 t;
        t.x = f2tf32(v.x); t.y = f2tf32(v.y); t.z = f2tf32(v.z); t.w = f2tf32(v.w);
        *(uint4*)&RAu[((row >> 4) * NKS1 + ks) * 128 + rg * 32 + p] = t;
    }
    for (int i = tid; i < TILE_M * 16; i += 256) {
        int row = i >> 4;
        int c4  = (i & 15) << 2;
        int col = 128 + c4;
        long long gr = r0 + row;
        float4 v = (gr < E) ? __ldg((const float4*)(edge + gr * 64 + c4))
                            : make_float4(0.f, 0.f, 0.f, 0.f);
        int ks = col >> 3;
        int rg = ((row >> 3) & 1) | (((col >> 2) & 1) << 1);
        int p  = (((row & 7) << 2) + 4 * (ks & 7) + ((rg & 2) << 3)) & 31;
        uint4 t;
        t.x = f2tf32(v.x); t.y = f2tf32(v.y); t.z = f2tf32(v.z); t.w = f2tf32(v.w);
        *(uint4*)&RAu[((row >> 4) * NKS1 + ks) * 128 + rg * 32 + p] = t;
    }
    // ---------------- stage B1 = W1 fragments -------------------------------
    for (int i = tid; i < KD1 * 32; i += 256) {
        int k  = i >> 5;
        int n4 = (i & 31) << 2;
        float4 w = __ldg((const float4*)(W1 + k * 128 + n4));
        int ks = k >> 3, rg = (k >> 2) & 1, k3 = k & 3;
        float wv[4] = {w.x, w.y, w.z, w.w};
        #pragma unroll
        for (int j = 0; j < 4; j++) {
            int n  = n4 + j;
            int nb = n >> 3;
            int p  = ((((n & 7) << 2) + k3) + 4 * (nb & 7) + ((nb & 8) << 1)) & 31;
            RBu[(nb * NKS1 + ks) * 64 + rg * 32 + p] = f2tf32(wv[j]);
        }
    }
    if (tid < 128) {
        s_b1[tid] = b1[tid];
        s_g[tid]  = gamma[tid];
        s_be[tid] = beta[tid];
        s_b2[tid] = b2[tid];
    }
    __syncthreads();

    // ---------------- GEMM1: h = x @ W1 -------------------------------------
    float acc[2][8][4];
    #pragma unroll
    for (int m2 = 0; m2 < 2; m2++)
        #pragma unroll
        for (int nb = 0; nb < 8; nb++)
            #pragma unroll
            for (int j = 0; j < 4; j++) acc[m2][nb][j] = 0.f;

    #pragma unroll 4
    for (int ks = 0; ks < NKS1; ks++) {
        uint32_t af[2][4];
        #pragma unroll
        for (int m2 = 0; m2 < 2; m2++)
            #pragma unroll
            for (int rg = 0; rg < 4; rg++)
                af[m2][rg] = RAu[((mt0 + m2) * NKS1 + ks) * 128 + rg * 32 +
                                 ((lane + 4 * (ks & 7) + ((rg & 2) << 3)) & 31)];
        #pragma unroll
        for (int nb = 0; nb < 8; nb++) {
            int nbg = nb0 + nb;
            int pb  = (lane + 4 * (nbg & 7) + ((nbg & 8) << 1)) & 31;
            uint32_t bf0 = RBu[(nbg * NKS1 + ks) * 64 + pb];
            uint32_t bf1 = RBu[(nbg * NKS1 + ks) * 64 + 32 + pb];
            mma8(acc[0][nb], af[0], bf0, bf1);
            mma8(acc[1][nb], af[1], bf0, bf1);
        }
    }

    // ---------------- bias + row stats (sum, sumsq) -------------------------
    float s_[2][2] = {{0.f, 0.f}, {0.f, 0.f}};
    float q_[2][2] = {{0.f, 0.f}, {0.f, 0.f}};
    #pragma unroll
    for (int m2 = 0; m2 < 2; m2++)
        #pragma unroll
        for (int nb = 0; nb < 8; nb++) {
            int n0 = (nb0 + nb) * 8 + tig * 2;
            float bb0 = s_b1[n0], bb1 = s_b1[n0 + 1];
            #pragma unroll
            for (int h = 0; h < 2; h++) {
                float v0 = acc[m2][nb][h * 2]     + bb0;
                float v1 = acc[m2][nb][h * 2 + 1] + bb1;
                acc[m2][nb][h * 2]     = v0;
                acc[m2][nb][h * 2 + 1] = v1;
                s_[m2][h] += v0 + v1;
                q_[m2][h] += v0 * v0 + v1 * v1;
            }
        }
    #pragma unroll
    for (int m2 = 0; m2 < 2; m2++)
        #pragma unroll
        for (int h = 0; h < 2; h++) {
            s_[m2][h] += __shfl_xor_sync(0xffffffffu, s_[m2][h], 1);
            s_[m2][h] += __shfl_xor_sync(0xffffffffu, s_[m2][h], 2);
            q_[m2][h] += __shfl_xor_sync(0xffffffffu, q_[m2][h], 1);
            q_[m2][h] += __shfl_xor_sync(0xffffffffu, q_[m2][h], 2);
        }
    if (tig == 0) {
        #pragma unroll
        for (int m2 = 0; m2 < 2; m2++)
            #pragma unroll
            for (int h = 0; h < 2; h++) {
                int row = mw * 32 + m2 * 16 + h * 8 + g;
                red[(0 * 2 + nw) * 128 + row] = s_[m2][h];
                red[(1 * 2 + nw) * 128 + row] = q_[m2][h];
            }
    }
    __syncthreads();   // GEMM1 fully retired CTA-wide; RA/RB reusable

    // ---------------- stage W2 fragments (into RB) --------------------------
    for (int i = tid; i < ND * 32; i += 256) {
        int k  = i >> 5;
        int n4 = (i & 31) << 2;
        float4 w = __ldg((const float4*)(W2 + k * 128 + n4));
        int ks = k >> 3, rg = (k >> 2) & 1, k3 = k & 3;
        float wv[4] = {w.x, w.y, w.z, w.w};
        #pragma unroll
        for (int j = 0; j < 4; j++) {
            int n  = n4 + j;
            int nb = n >> 3;
            int p  = ((((n & 7) << 2) + k3) + 4 * (nb & 7) + ((nb & 8) << 1)) & 31;
            RBu[(nb * NKS2 + ks) * 64 + rg * 32 + p] = f2tf32(wv[j]);
        }
    }

    // ---------------- LayerNorm + SiLU -> A2 fragments (into RA) ------------
    #pragma unroll
    for (int m2 = 0; m2 < 2; m2++)
        #pragma unroll
        for (int h = 0; h < 2; h++) {
            int row = mw * 32 + m2 * 16 + h * 8 + g;
            float mu = (red[0 * 128 + row] + red[1 * 128 + row]) * (1.f / 128.f);
            float ms = (red[2 * 128 + row] + red[3 * 128 + row]) * (1.f / 128.f);
            float var = ms - mu * mu;
            float rstd = rsqrtf(fmaxf(var, 0.f) + 1e-5f);
            #pragma unroll
            for (int nb = 0; nb < 8; nb++) {
                int n0 = (nb0 + nb) * 8 + tig * 2;
                float x0 = (acc[m2][nb][h * 2]     - mu) * rstd * s_g[n0]     + s_be[n0];
                float x1 = (acc[m2][nb][h * 2 + 1] - mu) * rstd * s_g[n0 + 1] + s_be[n0 + 1];
                uint2 t;
                t.x = f2tf32(silu_f(x0));
                t.y = f2tf32(silu_f(x1));
                int ksA = nb0 + nb;                  // k-col / 8 for GEMM2
                int rg  = h | ((tig >> 1) << 1);
                int lf  = g * 4 + ((tig * 2) & 3);
                int p   = (lf + 4 * (ksA & 7) + ((rg & 2) << 3)) & 31;
                *(uint2*)&RAu[((mt0 + m2) * NKS2 + ksA) * 128 + rg * 32 + p] = t;
            }
        }
    __syncthreads();

    // ---------------- GEMM2: y = a2 @ W2 ------------------------------------
    float acc2[2][8][4];
    #pragma unroll
    for (int m2 = 0; m2 < 2; m2++)
        #pragma unroll
        for (int nb = 0; nb < 8; nb++)
            #pragma unroll
            for (int j = 0; j < 4; j++) acc2[m2][nb][j] = 0.f;

    #pragma unroll 4
    for (int ks = 0; ks < NKS2; ks++) {
        uint32_t af[2][4];
        #pragma unroll
        for (int m2 = 0; m2 < 2; m2++)
            #pragma unroll
            for (int rg = 0; rg < 4; rg++)
                af[m2][rg] = RAu[((mt0 + m2) * NKS2 + ks) * 128 + rg * 32 +
                                 ((lane + 4 * (ks & 7) + ((rg & 2) << 3)) & 31)];
        #pragma unroll
        for (int nb = 0; nb < 8; nb++) {
            int nbg = nb0 + nb;
            int pb  = (lane + 4 * (nbg & 7) + ((nbg & 8) << 1)) & 31;
            uint32_t bf0 = RBu[(nbg * NKS2 + ks) * 64 + pb];
            uint32_t bf1 = RBu[(nbg * NKS2 + ks) * 64 + 32 + pb];
            mma8(acc2[0][nb], af[0], bf0, bf1);
            mma8(acc2[1][nb], af[1], bf0, bf1);
        }
    }

    // ---------------- epilogue: +b2, SiLU, store ----------------------------
    #pragma unroll
    for (int m2 = 0; m2 < 2; m2++)
        #pragma unroll
        for (int h = 0; h < 2; h++) {
            long long row = r0 + mw * 32 + m2 * 16 + h * 8 + g;
            if (row < E) {
                #pragma unroll
                for (int nb = 0; nb < 8; nb++) {
                    int n0 = (nb0 + nb) * 8 + tig * 2;
                    float x0 = acc2[m2][nb][h * 2]     + s_b2[n0];
                    float x1 = acc2[m2][nb][h * 2 + 1] + s_b2[n0 + 1];
                    float2 o;
                    o.x = silu_f(x0);
                    o.y = silu_f(x1);
                    *(float2*)(out + row * 128 + n0) = o;
                }
            }
        }
}

extern "C" void kernel_launch(void* const* d_in, const int* in_sizes, int n_in,
                              void* d_out, int out_size) {
    const float* src   = (const float*)d_in[0];
    const float* edge  = (const float*)d_in[1];
    const float* W1    = (const float*)d_in[2];
    const float* b1    = (const float*)d_in[3];
    const float* gamma = (const float*)d_in[4];
    const float* beta  = (const float*)d_in[5];
    const float* W2    = (const float*)d_in[6];
    const float* b2    = (const float*)d_in[7];
    float* out = (float*)d_out;

    int E = in_sizes[0] / 128;
    int grid = (E + TILE_M - 1) / TILE_M;

    static bool attr_set = false;
    if (!attr_set) {
        cudaFuncSetAttribute(edge_mlp_kernel,
                             cudaFuncAttributeMaxDynamicSharedMemorySize,
                             SMEM_BYTES);
        attr_set = true;
    }
    edge_mlp_kernel<<<grid, 256, SMEM_BYTES>>>(src, edge, W1, b1, gamma, beta,
                                               W2, b2, out, E);
}

// round 5
// speedup vs baseline: 1.7621x; 1.7621x over previous
#include <cuda_runtime.h>
#include <cstdint>

// ============================================================================
// EdgeMLP: concat -> GEMM1(tf32 mma.sync) -> LayerNorm -> SiLU ->
//          GEMM2(tf32 mma.sync) -> SiLU -> out
// Baseline-PTX only (toolchain emits .target sm_103; no tcgen05/cluster).
// 1 CTA = 128 rows. 512 threads = 16 warps in 4(M) x 4(N) layout.
// All operands staged in SMEM in mma-fragment layout with bank-rotation skew.
// ============================================================================

#define TILE_M 128
#define KD1    192
#define ND     128
#define NKS1   24     // 192/8 k-steps for GEMM1
#define NKS2   16     // 128/8 k-steps for GEMM2
#define NTHR   512

// dynamic SMEM layout (float offsets)
#define R0_OFF   0        // 24576 floats: A1 frags -> reused as A2 frags (16384)
#define R1_OFF   24576    // 24576 floats: B1 frags -> reused as W2 frags (16384)
#define MISC_OFF 49152    // b1,g,be,b2 (4*128) + red (2*4*128)
#define SMEM_FLOATS (49152 + 512 + 1024)
#define SMEM_BYTES  (SMEM_FLOATS * 4)

static __device__ __forceinline__ uint32_t f2tf32(float f) {
    uint32_t r;
    asm("cvt.rna.tf32.f32 %0, %1;" : "=r"(r) : "f"(f));
    return r;
}
static __device__ __forceinline__ float silu_f(float x) {
    return x / (1.f + __expf(-x));
}
static __device__ __forceinline__ void mma8(float* c, const uint32_t* a,
                                            uint32_t b0, uint32_t b1) {
    asm volatile(
        "mma.sync.aligned.m16n8k8.row.col.f32.tf32.tf32.f32 "
        "{%0,%1,%2,%3},{%4,%5,%6,%7},{%8,%9},{%0,%1,%2,%3};\n"
        : "+f"(c[0]), "+f"(c[1]), "+f"(c[2]), "+f"(c[3])
        : "r"(a[0]), "r"(a[1]), "r"(a[2]), "r"(a[3]), "r"(b0), "r"(b1));
}

// Fragment-layout addressing (unchanged from R2):
// A-side region: idx = ((mt*NKS + ks)*4 + reg)*32 + posA
//   posA = (lane_frag + 4*(ks&7) + 16*(reg>>1)) & 31   (bank-rotation skew)
//   lane_frag = (row&7)*4 + (col&3); reg = (row>>3)&1 | ((col>>2)&1)<<1
// B-side region: idx = ((nb*NKS + ks)*2 + reg)*32 + posB
//   posB = (lane_frag + 4*(nb&7) + 16*((nb>>3)&1)) & 31
//   lane_frag = (n&7)*4 + (k&3); reg = (k>>2)&1

__global__ void __launch_bounds__(NTHR, 1)
edge_mlp_kernel(const float* __restrict__ src, const float* __restrict__ edge,
                const float* __restrict__ W1, const float* __restrict__ b1,
                const float* __restrict__ gamma, const float* __restrict__ beta,
                const float* __restrict__ W2, const float* __restrict__ b2,
                float* __restrict__ out, int E) {
    extern __shared__ float sm[];
    float* s_b1 = sm + MISC_OFF;
    float* s_g  = s_b1 + 128;
    float* s_be = s_g + 128;
    float* s_b2 = s_be + 128;
    float* red  = s_b2 + 128;     // [stat(2)][nw(4)][row(128)]

    uint32_t* RAu = (uint32_t*)(sm + R0_OFF);
    uint32_t* RBu = (uint32_t*)(sm + R1_OFF);

    const int tid  = threadIdx.x;
    const int lane = tid & 31;
    const int wid  = tid >> 5;
    const int mw   = wid >> 2;    // 0..3 : rows 32*mw .. 32*mw+31
    const int nw   = wid & 3;     // 0..3 : cols 32*nw .. 32*nw+31
    const int g    = lane >> 2;
    const int tig  = lane & 3;
    const int mt0  = mw * 2;
    const int nb0  = nw * 4;

    const long long r0 = (long long)blockIdx.x * TILE_M;

    // ---------------- stage A1 (concat src|edge) as tf32 fragments ----------
    #pragma unroll
    for (int i = tid; i < TILE_M * 32; i += NTHR) {
        int row = i >> 5;
        int c4  = (i & 31) << 2;
        long long gr = r0 + row;
        float4 v = (gr < E) ? __ldg((const float4*)(src + gr * 128 + c4))
                            : make_float4(0.f, 0.f, 0.f, 0.f);
        int ks = c4 >> 3;
        int rg = ((row >> 3) & 1) | (((c4 >> 2) & 1) << 1);
        int p  = (((row & 7) << 2) + 4 * (ks & 7) + ((rg & 2) << 3)) & 31;
        uint4 t;
        t.x = f2tf32(v.x); t.y = f2tf32(v.y); t.z = f2tf32(v.z); t.w = f2tf32(v.w);
        *(uint4*)&RAu[((row >> 4) * NKS1 + ks) * 128 + rg * 32 + p] = t;
    }
    #pragma unroll
    for (int i = tid; i < TILE_M * 16; i += NTHR) {
        int row = i >> 4;
        int c4  = (i & 15) << 2;
        int col = 128 + c4;
        long long gr = r0 + row;
        float4 v = (gr < E) ? __ldg((const float4*)(edge + gr * 64 + c4))
                            : make_float4(0.f, 0.f, 0.f, 0.f);
        int ks = col >> 3;
        int rg = ((row >> 3) & 1) | (((col >> 2) & 1) << 1);
        int p  = (((row & 7) << 2) + 4 * (ks & 7) + ((rg & 2) << 3)) & 31;
        uint4 t;
        t.x = f2tf32(v.x); t.y = f2tf32(v.y); t.z = f2tf32(v.z); t.w = f2tf32(v.w);
        *(uint4*)&RAu[((row >> 4) * NKS1 + ks) * 128 + rg * 32 + p] = t;
    }
    // ---------------- stage B1 = W1 fragments -------------------------------
    #pragma unroll
    for (int i = tid; i < KD1 * 32; i += NTHR) {
        int k  = i >> 5;
        int n4 = (i & 31) << 2;
        float4 w = __ldg((const float4*)(W1 + k * 128 + n4));
        int ks = k >> 3, rg = (k >> 2) & 1, k3 = k & 3;
        float wv[4] = {w.x, w.y, w.z, w.w};
        #pragma unroll
        for (int j = 0; j < 4; j++) {
            int n  = n4 + j;
            int nb = n >> 3;
            int p  = ((((n & 7) << 2) + k3) + 4 * (nb & 7) + ((nb & 8) << 1)) & 31;
            RBu[(nb * NKS1 + ks) * 64 + rg * 32 + p] = f2tf32(wv[j]);
        }
    }
    if (tid < 128) {
        s_b1[tid] = b1[tid];
        s_g[tid]  = gamma[tid];
        s_be[tid] = beta[tid];
        s_b2[tid] = b2[tid];
    }
    __syncthreads();

    // ---------------- GEMM1: h = x @ W1 -------------------------------------
    float acc[2][4][4];
    #pragma unroll
    for (int m2 = 0; m2 < 2; m2++)
        #pragma unroll
        for (int nb = 0; nb < 4; nb++)
            #pragma unroll
            for (int j = 0; j < 4; j++) acc[m2][nb][j] = 0.f;

    #pragma unroll 8
    for (int ks = 0; ks < NKS1; ks++) {
        uint32_t af[2][4];
        #pragma unroll
        for (int m2 = 0; m2 < 2; m2++)
            #pragma unroll
            for (int rg = 0; rg < 4; rg++)
                af[m2][rg] = RAu[((mt0 + m2) * NKS1 + ks) * 128 + rg * 32 +
                                 ((lane + 4 * (ks & 7) + ((rg & 2) << 3)) & 31)];
        #pragma unroll
        for (int nb = 0; nb < 4; nb++) {
            int nbg = nb0 + nb;
            int pb  = (lane + 4 * (nbg & 7) + ((nbg & 8) << 1)) & 31;
            uint32_t bf0 = RBu[(nbg * NKS1 + ks) * 64 + pb];
            uint32_t bf1 = RBu[(nbg * NKS1 + ks) * 64 + 32 + pb];
            mma8(acc[0][nb], af[0], bf0, bf1);
            mma8(acc[1][nb], af[1], bf0, bf1);
        }
    }

    // ---------------- bias + row stats (sum, sumsq) -------------------------
    float s_[2][2] = {{0.f, 0.f}, {0.f, 0.f}};
    float q_[2][2] = {{0.f, 0.f}, {0.f, 0.f}};
    #pragma unroll
    for (int m2 = 0; m2 < 2; m2++)
        #pragma unroll
        for (int nb = 0; nb < 4; nb++) {
            int n0 = (nb0 + nb) * 8 + tig * 2;
            float bb0 = s_b1[n0], bb1 = s_b1[n0 + 1];
            #pragma unroll
            for (int h = 0; h < 2; h++) {
                float v0 = acc[m2][nb][h * 2]     + bb0;
                float v1 = acc[m2][nb][h * 2 + 1] + bb1;
                acc[m2][nb][h * 2]     = v0;
                acc[m2][nb][h * 2 + 1] = v1;
                s_[m2][h] += v0 + v1;
                q_[m2][h] += v0 * v0 + v1 * v1;
            }
        }
    #pragma unroll
    for (int m2 = 0; m2 < 2; m2++)
        #pragma unroll
        for (int h = 0; h < 2; h++) {
            s_[m2][h] += __shfl_xor_sync(0xffffffffu, s_[m2][h], 1);
            s_[m2][h] += __shfl_xor_sync(0xffffffffu, s_[m2][h], 2);
            q_[m2][h] += __shfl_xor_sync(0xffffffffu, q_[m2][h], 1);
            q_[m2][h] += __shfl_xor_sync(0xffffffffu, q_[m2][h], 2);
        }
    if (tig == 0) {
        #pragma unroll
        for (int m2 = 0; m2 < 2; m2++)
            #pragma unroll
            for (int h = 0; h < 2; h++) {
                int row = mw * 32 + m2 * 16 + h * 8 + g;
                red[(0 * 4 + nw) * 128 + row] = s_[m2][h];
                red[(1 * 4 + nw) * 128 + row] = q_[m2][h];
            }
    }
    __syncthreads();   // GEMM1 fully retired CTA-wide; RA/RB reusable

    // ---------------- stage W2 fragments (into RB) --------------------------
    #pragma unroll
    for (int i = tid; i < ND * 32; i += NTHR) {
        int k  = i >> 5;
        int n4 = (i & 31) << 2;
        float4 w = __ldg((const float4*)(W2 + k * 128 + n4));
        int ks = k >> 3, rg = (k >> 2) & 1, k3 = k & 3;
        float wv[4] = {w.x, w.y, w.z, w.w};
        #pragma unroll
        for (int j = 0; j < 4; j++) {
            int n  = n4 + j;
            int nb = n >> 3;
            int p  = ((((n & 7) << 2) + k3) + 4 * (nb & 7) + ((nb & 8) << 1)) & 31;
            RBu[(nb * NKS2 + ks) * 64 + rg * 32 + p] = f2tf32(wv[j]);
        }
    }

    // ---------------- LayerNorm + SiLU -> A2 fragments (into RA) ------------
    #pragma unroll
    for (int m2 = 0; m2 < 2; m2++)
        #pragma unroll
        for (int h = 0; h < 2; h++) {
            int row = mw * 32 + m2 * 16 + h * 8 + g;
            float mu = (red[0 * 128 + row] + red[1 * 128 + row] +
                        red[2 * 128 + row] + red[3 * 128 + row]) * (1.f / 128.f);
            float ms = (red[4 * 128 + row] + red[5 * 128 + row] +
                        red[6 * 128 + row] + red[7 * 128 + row]) * (1.f / 128.f);
            float var = ms - mu * mu;
            float rstd = rsqrtf(fmaxf(var, 0.f) + 1e-5f);
            #pragma unroll
            for (int nb = 0; nb < 4; nb++) {
                int n0 = (nb0 + nb) * 8 + tig * 2;
                float x0 = (acc[m2][nb][h * 2]     - mu) * rstd * s_g[n0]     + s_be[n0];
                float x1 = (acc[m2][nb][h * 2 + 1] - mu) * rstd * s_g[n0 + 1] + s_be[n0 + 1];
                uint2 t;
                t.x = f2tf32(silu_f(x0));
                t.y = f2tf32(silu_f(x1));
                int ksA = nb0 + nb;                  // k-col / 8 for GEMM2
                int rg  = h | ((tig >> 1) << 1);
                int lf  = g * 4 + ((tig * 2) & 3);
                int p   = (lf + 4 * (ksA & 7) + ((rg & 2) << 3)) & 31;
                *(uint2*)&RAu[((mt0 + m2) * NKS2 + ksA) * 128 + rg * 32 + p] = t;
            }
        }
    __syncthreads();

    // ---------------- GEMM2: y = a2 @ W2 ------------------------------------
    float acc2[2][4][4];
    #pragma unroll
    for (int m2 = 0; m2 < 2; m2++)
        #pragma unroll
        for (int nb = 0; nb < 4; nb++)
            #pragma unroll
            for (int j = 0; j < 4; j++) acc2[m2][nb][j] = 0.f;

    #pragma unroll 8
    for (int ks = 0; ks < NKS2; ks++) {
        uint32_t af[2][4];
        #pragma unroll
        for (int m2 = 0; m2 < 2; m2++)
            #pragma unroll
            for (int rg = 0; rg < 4; rg++)
                af[m2][rg] = RAu[((mt0 + m2) * NKS2 + ks) * 128 + rg * 32 +
                                 ((lane + 4 * (ks & 7) + ((rg & 2) << 3)) & 31)];
        #pragma unroll
        for (int nb = 0; nb < 4; nb++) {
            int nbg = nb0 + nb;
            int pb  = (lane + 4 * (nbg & 7) + ((nbg & 8) << 1)) & 31;
            uint32_t bf0 = RBu[(nbg * NKS2 + ks) * 64 + pb];
            uint32_t bf1 = RBu[(nbg * NKS2 + ks) * 64 + 32 + pb];
            mma8(acc2[0][nb], af[0], bf0, bf1);
            mma8(acc2[1][nb], af[1], bf0, bf1);
        }
    }

    // ---------------- epilogue: +b2, SiLU, store ----------------------------
    #pragma unroll
    for (int m2 = 0; m2 < 2; m2++)
        #pragma unroll
        for (int h = 0; h < 2; h++) {
            long long row = r0 + mw * 32 + m2 * 16 + h * 8 + g;
            if (row < E) {
                #pragma unroll
                for (int nb = 0; nb < 4; nb++) {
                    int n0 = (nb0 + nb) * 8 + tig * 2;
                    float x0 = acc2[m2][nb][h * 2]     + s_b2[n0];
                    float x1 = acc2[m2][nb][h * 2 + 1] + s_b2[n0 + 1];
                    float2 o;
                    o.x = silu_f(x0);
                    o.y = silu_f(x1);
                    *(float2*)(out + row * 128 + n0) = o;
                }
            }
        }
}

extern "C" void kernel_launch(void* const* d_in, const int* in_sizes, int n_in,
                              void* d_out, int out_size) {
    const float* src   = (const float*)d_in[0];
    const float* edge  = (const float*)d_in[1];
    const float* W1    = (const float*)d_in[2];
    const float* b1    = (const float*)d_in[3];
    const float* gamma = (const float*)d_in[4];
    const float* beta  = (const float*)d_in[5];
    const float* W2    = (const float*)d_in[6];
    const float* b2    = (const float*)d_in[7];
    float* out = (float*)d_out;

    int E = in_sizes[0] / 128;
    int grid = (E + TILE_M - 1) / TILE_M;

    static bool attr_set = false;
    if (!attr_set) {
        cudaFuncSetAttribute(edge_mlp_kernel,
                             cudaFuncAttributeMaxDynamicSharedMemorySize,
                             SMEM_BYTES);
        attr_set = true;
    }
    edge_mlp_kernel<<<grid, NTHR, SMEM_BYTES>>>(src, edge, W1, b1, gamma, beta,
                                                W2, b2, out, E);
}